// round 3
// baseline (speedup 1.0000x reference)
#include <cuda_runtime.h>

#define NB 256
#define NT 512
#define NI 300
#define NH 128

// 64 MiB scratch for precomputed input projections xp[b][t][h]
__device__ float g_xp[NB * NT * NH];

// ---------------------------------------------------------------------------
// Phase 1: xp = x @ W_ih^T + (b_ih + b_hh)
// M = NB*NT = 131072, N = NH = 128, K = NI = 300
// Tiles: BM=128, BN=128 (=N, single column block), BK=20 (300 = 15*20 exact)
// 256 threads, each computes an 8x8 register micro-tile.
// ---------------------------------------------------------------------------
#define BM 128
#define BN 128
#define BK 20

__global__ __launch_bounds__(256, 1) void gemm_xp_kernel(
    const float* __restrict__ x, const float* __restrict__ Wih,
    const float* __restrict__ bih, const float* __restrict__ bhh)
{
    __shared__ float xs[BK][BM];   // k-major for vectorized fragment loads
    __shared__ float ws[BK][BN];
    __shared__ float bias_s[NH];

    const int tid = threadIdx.x;
    const int m0 = blockIdx.x * BM;
    if (tid < NH) bias_s[tid] = bih[tid] + bhh[tid];

    const int tr = tid >> 4;   // 0..15 -> rows tr*8 .. tr*8+7
    const int tc = tid & 15;   // 0..15 -> cols tc*8 .. tc*8+7

    float acc[8][8];
#pragma unroll
    for (int i = 0; i < 8; i++)
#pragma unroll
        for (int jj = 0; jj < 8; jj++) acc[i][jj] = 0.f;

    for (int k0 = 0; k0 < NI; k0 += BK) {
        // load x tile (transposed to k-major)
#pragma unroll
        for (int it = 0; it < (BM * BK) / 256; it++) {
            int idx = tid + it * 256;
            int r = idx / BK, kk = idx % BK;
            xs[kk][r] = x[(m0 + r) * NI + k0 + kk];
        }
        // load W_ih tile (transposed to k-major)
#pragma unroll
        for (int it = 0; it < (BN * BK) / 256; it++) {
            int idx = tid + it * 256;
            int r = idx / BK, kk = idx % BK;
            ws[kk][r] = Wih[r * NI + k0 + kk];
        }
        __syncthreads();

#pragma unroll 4
        for (int kk = 0; kk < BK; kk++) {
            float4 a0 = *(const float4*)&xs[kk][tr * 8];
            float4 a1 = *(const float4*)&xs[kk][tr * 8 + 4];
            float4 b0 = *(const float4*)&ws[kk][tc * 8];
            float4 b1 = *(const float4*)&ws[kk][tc * 8 + 4];
            float av[8] = {a0.x, a0.y, a0.z, a0.w, a1.x, a1.y, a1.z, a1.w};
            float bv[8] = {b0.x, b0.y, b0.z, b0.w, b1.x, b1.y, b1.z, b1.w};
#pragma unroll
            for (int i = 0; i < 8; i++)
#pragma unroll
                for (int jj = 0; jj < 8; jj++)
                    acc[i][jj] = fmaf(av[i], bv[jj], acc[i][jj]);
        }
        __syncthreads();
    }

    // epilogue: add bias, write xp
#pragma unroll
    for (int i = 0; i < 8; i++) {
        int r = m0 + tr * 8 + i;
        float* p = &g_xp[r * NH + tc * 8];
#pragma unroll
        for (int jj = 0; jj < 8; jj++)
            p[jj] = acc[i][jj] + bias_s[tc * 8 + jj];
    }
}

// ---------------------------------------------------------------------------
// Phase 2: sequential scan. Each CTA owns 2 batch rows.
// W_hh kept transposed in SMEM (wt[k][j] = W_hh[j][k]) with stride 132 to
// avoid bank conflicts. h double-buffered in SMEM, one barrier per step.
// xp for step t+1 prefetched into registers during step t's compute.
// Final FC (128 -> 2) fused as 4 warp reductions.
// ---------------------------------------------------------------------------
#define WT_STRIDE 132

__global__ __launch_bounds__(128, 1) void rnn_scan_kernel(
    const float* __restrict__ Whh, const float* __restrict__ fcw,
    const float* __restrict__ fcb, float* __restrict__ out)
{
    extern __shared__ float wt[];            // [NH * WT_STRIDE]
    __shared__ float hbuf[2][2][NH];         // [pingpong][row][j]

    const int j = threadIdx.x;
    const int b0 = blockIdx.x * 2;

    // load + transpose W_hh: coalesced global reads, padded smem stores
#pragma unroll 8
    for (int it = 0; it < NH; it++) {
        wt[j * WT_STRIDE + it] = Whh[it * NH + j];   // wt[k=j? no: see note]
    }
    // NOTE on the above: thread j writes wt[j*WT_STRIDE + it] = Whh[it*NH + j],
    // i.e. wt[a*WT_STRIDE + b] = Whh[b*NH + a]  => wt[k*WT_STRIDE + jj] = Whh[jj*NH + k].
    // So the inner loop read wt[k*WT_STRIDE + j] = W_hh[j][k] as required.

    hbuf[0][0][j] = 0.f;
    hbuf[0][1][j] = 0.f;
    __syncthreads();

    const float* xp0 = g_xp + b0 * (NT * NH);
    const float* xp1 = xp0 + (NT * NH);

    float nx0 = xp0[j];
    float nx1 = xp1[j];

    int cur = 0;
    for (int t = 0; t < NT; t++) {
        // two accumulator chains per row: saturates FFMA rt=2 at lat=4
        float a0a = nx0, a1a = nx1;
        float a0b = 0.f, a1b = 0.f;

        // prefetch next timestep's xp (hidden under the 512-cycle FMA block)
        if (t + 1 < NT) {
            nx0 = xp0[(t + 1) * NH + j];
            nx1 = xp1[(t + 1) * NH + j];
        }

        const float* h0 = hbuf[cur][0];
        const float* h1 = hbuf[cur][1];
#pragma unroll
        for (int k = 0; k < NH; k += 8) {
            float4 ha0 = *(const float4*)(h0 + k);
            float4 hb0 = *(const float4*)(h1 + k);
            float4 ha1 = *(const float4*)(h0 + k + 4);
            float4 hb1 = *(const float4*)(h1 + k + 4);
            float w0 = wt[(k + 0) * WT_STRIDE + j];
            float w1 = wt[(k + 1) * WT_STRIDE + j];
            float w2 = wt[(k + 2) * WT_STRIDE + j];
            float w3 = wt[(k + 3) * WT_STRIDE + j];
            float w4 = wt[(k + 4) * WT_STRIDE + j];
            float w5 = wt[(k + 5) * WT_STRIDE + j];
            float w6 = wt[(k + 6) * WT_STRIDE + j];
            float w7 = wt[(k + 7) * WT_STRIDE + j];
            a0a = fmaf(ha0.x, w0, a0a);  a1a = fmaf(hb0.x, w0, a1a);
            a0b = fmaf(ha0.y, w1, a0b);  a1b = fmaf(hb0.y, w1, a1b);
            a0a = fmaf(ha0.z, w2, a0a);  a1a = fmaf(hb0.z, w2, a1a);
            a0b = fmaf(ha0.w, w3, a0b);  a1b = fmaf(hb0.w, w3, a1b);
            a0a = fmaf(ha1.x, w4, a0a);  a1a = fmaf(hb1.x, w4, a1a);
            a0b = fmaf(ha1.y, w5, a0b);  a1b = fmaf(hb1.y, w5, a1b);
            a0a = fmaf(ha1.z, w6, a0a);  a1a = fmaf(hb1.z, w6, a1a);
            a0b = fmaf(ha1.w, w7, a0b);  a1b = fmaf(hb1.w, w7, a1b);
        }

        int nxt = cur ^ 1;
        hbuf[nxt][0][j] = tanhf(a0a + a0b);
        hbuf[nxt][1][j] = tanhf(a1a + a1b);
        __syncthreads();
        cur = nxt;
    }

    // fused FC: warp w handles (row = w>>1, class = w&1)
    const int w = j >> 5, lane = j & 31;
    const int row = w >> 1, cls = w & 1;
    const float* h = hbuf[cur][row];
    float s = 0.f;
#pragma unroll
    for (int kk = 0; kk < NH; kk += 32)
        s += h[kk + lane] * fcw[cls * NH + kk + lane];
#pragma unroll
    for (int off = 16; off > 0; off >>= 1)
        s += __shfl_xor_sync(0xffffffffu, s, off);
    if (lane == 0) out[(b0 + row) * 2 + cls] = s + fcb[cls];
}

// ---------------------------------------------------------------------------
extern "C" void kernel_launch(void* const* d_in, const int* in_sizes, int n_in,
                              void* d_out, int out_size)
{
    const float* x   = (const float*)d_in[0];
    const float* Wih = (const float*)d_in[1];
    const float* Whh = (const float*)d_in[2];
    const float* bih = (const float*)d_in[3];
    const float* bhh = (const float*)d_in[4];
    const float* fcw = (const float*)d_in[5];
    const float* fcb = (const float*)d_in[6];
    float* out = (float*)d_out;

    (void)in_sizes; (void)n_in; (void)out_size;

    const int scan_smem = NH * WT_STRIDE * (int)sizeof(float);  // 67584 B
    cudaFuncSetAttribute(rnn_scan_kernel,
                         cudaFuncAttributeMaxDynamicSharedMemorySize, scan_smem);

    gemm_xp_kernel<<<(NB * NT) / BM, 256>>>(x, Wih, bih, bhh);
    rnn_scan_kernel<<<NB / 2, 128, scan_smem>>>(Whh, fcw, fcb, out);
}

// round 4
// speedup vs baseline: 1.4019x; 1.4019x over previous
#include <cuda_runtime.h>

#define NB 256
#define NT 512
#define NI 300
#define NH 128

typedef unsigned long long u64t;

// 64 MiB scratch for precomputed input projections xp[b][t][h]
__device__ float g_xp[NB * NT * NH];

// ---------------- packed f32x2 helpers (sm_103a) ----------------
__device__ __forceinline__ u64t pack2(float lo, float hi) {
    u64t r;
    asm("mov.b64 %0, {%1, %2};" : "=l"(r) : "f"(lo), "f"(hi));
    return r;
}
__device__ __forceinline__ void unpack2(u64t v, float& lo, float& hi) {
    asm("mov.b64 {%0, %1}, %2;" : "=f"(lo), "=f"(hi) : "l"(v));
}
__device__ __forceinline__ void ffma2(u64t& d, u64t a, u64t b) {
    asm("fma.rn.f32x2 %0, %1, %2, %0;" : "+l"(d) : "l"(a), "l"(b));
}

// ---------------------------------------------------------------------------
// Phase 1: xp = x @ W_ih^T + (b_ih + b_hh)
// M = 131072, N = 128, K = 300. BM=128, BN=128, BK=20 (300 = 15*20).
// 256 threads, 8x8 micro-tile per thread, FFMA2 inner product (pack along n),
// register-staged software pipeline on the gmem tile loads.
// ---------------------------------------------------------------------------
#define BM 128
#define BN 128
#define BK 20

__global__ __launch_bounds__(256, 1) void gemm_xp_kernel(
    const float* __restrict__ x, const float* __restrict__ Wih,
    const float* __restrict__ bih, const float* __restrict__ bhh)
{
    __shared__ __align__(16) float xs[BK][BM];   // k-major
    __shared__ __align__(16) float ws[BK][BN];
    __shared__ float bias_s[NH];

    const int tid = threadIdx.x;
    const int m0 = blockIdx.x * BM;
    if (tid < NH) bias_s[tid] = bih[tid] + bhh[tid];

    const int tr = tid >> 4;   // rows tr*8 .. tr*8+7
    const int tc = tid & 15;   // cols tc*8 .. tc*8+7

    u64t acc2[8][4];
#pragma unroll
    for (int i = 0; i < 8; i++)
#pragma unroll
        for (int p = 0; p < 4; p++) acc2[i][p] = 0ull;

    float rx[10], rw[10];
    // preload tile 0
#pragma unroll
    for (int it = 0; it < 10; it++) {
        int idx = tid + it * 256;
        int r = idx / BK, kk = idx % BK;
        rx[it] = x[(m0 + r) * NI + kk];
        rw[it] = Wih[r * NI + kk];
    }

    for (int tile = 0; tile < NI / BK; tile++) {
        // commit staged tile to smem
#pragma unroll
        for (int it = 0; it < 10; it++) {
            int idx = tid + it * 256;
            int r = idx / BK, kk = idx % BK;
            xs[kk][r] = rx[it];
            ws[kk][r] = rw[it];
        }
        __syncthreads();

        // stage next tile (LDG latency hidden under inner product)
        if (tile + 1 < NI / BK) {
            int k0 = (tile + 1) * BK;
#pragma unroll
            for (int it = 0; it < 10; it++) {
                int idx = tid + it * 256;
                int r = idx / BK, kk = idx % BK;
                rx[it] = x[(m0 + r) * NI + k0 + kk];
                rw[it] = Wih[r * NI + k0 + kk];
            }
        }

#pragma unroll 4
        for (int kk = 0; kk < BK; kk++) {
            float4 a0 = *(const float4*)&xs[kk][tr * 8];
            float4 a1 = *(const float4*)&xs[kk][tr * 8 + 4];
            // b-fragment directly as packed pairs
            ulonglong2 bq0 = *(const ulonglong2*)&ws[kk][tc * 8];
            ulonglong2 bq1 = *(const ulonglong2*)&ws[kk][tc * 8 + 4];
            u64t bp[4] = {bq0.x, bq0.y, bq1.x, bq1.y};
            float av[8] = {a0.x, a0.y, a0.z, a0.w, a1.x, a1.y, a1.z, a1.w};
#pragma unroll
            for (int i = 0; i < 8; i++) {
                u64t ap = pack2(av[i], av[i]);
#pragma unroll
                for (int p = 0; p < 4; p++)
                    ffma2(acc2[i][p], ap, bp[p]);
            }
        }
        __syncthreads();
    }

    // epilogue: unpack, add bias, store
#pragma unroll
    for (int i = 0; i < 8; i++) {
        int r = m0 + tr * 8 + i;
        float* pdst = &g_xp[r * NH + tc * 8];
#pragma unroll
        for (int p = 0; p < 4; p++) {
            float lo, hi;
            unpack2(acc2[i][p], lo, hi);
            float2 v;
            v.x = lo + bias_s[tc * 8 + 2 * p];
            v.y = hi + bias_s[tc * 8 + 2 * p + 1];
            *(float2*)(pdst + 2 * p) = v;
        }
    }
}

// ---------------------------------------------------------------------------
// Phase 2: sequential scan. 128 CTAs x 128 threads, 2 batch rows per CTA.
// Thread j keeps row j of W_hh in 128 registers (64 packed f32x2 pairs) —
// zero weight LDS per step. h double-buffered in static smem; loads are
// warp-broadcast ulonglong2 (16B). 128 FFMA2/step/thread. xp prefetched at
// distance 2 (step ~300cy < DRAM 577cy, so distance 1 would expose latency).
// ---------------------------------------------------------------------------
__global__ __launch_bounds__(128, 1) void rnn_scan_kernel(
    const float* __restrict__ Whh, const float* __restrict__ fcw,
    const float* __restrict__ fcb, float* __restrict__ out)
{
    __shared__ __align__(16) float hbuf[2][2][NH];

    const int j = threadIdx.x;
    const int b0 = blockIdx.x * 2;

    // row j of W_hh -> 64 packed pairs {w[2i], w[2i+1]} in registers
    u64t w2[64];
    const u64t* wrow = (const u64t*)(Whh + j * NH);
#pragma unroll
    for (int i = 0; i < 64; i++) w2[i] = wrow[i];

    hbuf[0][0][j] = 0.f;
    hbuf[0][1][j] = 0.f;
    __syncthreads();

    const float* __restrict__ xp0 = g_xp + b0 * (NT * NH);
    const float* __restrict__ xp1 = xp0 + (NT * NH);

    // prefetch depth 2
    float nx0a = xp0[j],      nx1a = xp1[j];
    float nx0b = xp0[NH + j], nx1b = xp1[NH + j];

    int cur = 0;
    for (int t = 0; t < NT; t++) {
        float x0 = nx0a, x1 = nx1a;
        nx0a = nx0b; nx1a = nx1b;
        if (t + 2 < NT) {
            nx0b = xp0[(t + 2) * NH + j];
            nx1b = xp1[(t + 2) * NH + j];
        }

        // two packed accumulator chains per row
        u64t c00 = pack2(x0, 0.f), c01 = 0ull;
        u64t c10 = pack2(x1, 0.f), c11 = 0ull;

        const float* h0 = hbuf[cur][0];
        const float* h1 = hbuf[cur][1];
#pragma unroll
        for (int k = 0; k < NH; k += 4) {
            ulonglong2 p = *(const ulonglong2*)(h0 + k);   // {h[k],h[k+1]},{h[k+2],h[k+3]}
            ulonglong2 q = *(const ulonglong2*)(h1 + k);
            ffma2(c00, p.x, w2[k / 2]);
            ffma2(c10, q.x, w2[k / 2]);
            ffma2(c01, p.y, w2[k / 2 + 1]);
            ffma2(c11, q.y, w2[k / 2 + 1]);
        }

        float l0, h0v, l1, h1v, l2, h2v, l3, h3v;
        unpack2(c00, l0, h0v);
        unpack2(c01, l1, h1v);
        unpack2(c10, l2, h2v);
        unpack2(c11, l3, h3v);
        float r0 = (l0 + h0v) + (l1 + h1v);
        float r1 = (l2 + h2v) + (l3 + h3v);

        int nxt = cur ^ 1;
        hbuf[nxt][0][j] = tanhf(r0);
        hbuf[nxt][1][j] = tanhf(r1);
        __syncthreads();
        cur = nxt;
    }

    // fused FC (128 -> 2): warp w handles (row = w>>1, class = w&1)
    const int w = j >> 5, lane = j & 31;
    const int row = w >> 1, cls = w & 1;
    const float* h = hbuf[cur][row];
    float s = 0.f;
#pragma unroll
    for (int kk = 0; kk < NH; kk += 32)
        s += h[kk + lane] * fcw[cls * NH + kk + lane];
#pragma unroll
    for (int off = 16; off > 0; off >>= 1)
        s += __shfl_xor_sync(0xffffffffu, s, off);
    if (lane == 0) out[(b0 + row) * 2 + cls] = s + fcb[cls];
}

// ---------------------------------------------------------------------------
extern "C" void kernel_launch(void* const* d_in, const int* in_sizes, int n_in,
                              void* d_out, int out_size)
{
    const float* x   = (const float*)d_in[0];
    const float* Wih = (const float*)d_in[1];
    const float* Whh = (const float*)d_in[2];
    const float* bih = (const float*)d_in[3];
    const float* bhh = (const float*)d_in[4];
    const float* fcw = (const float*)d_in[5];
    const float* fcb = (const float*)d_in[6];
    float* out = (float*)d_out;

    (void)in_sizes; (void)n_in; (void)out_size;

    gemm_xp_kernel<<<(NB * NT) / BM, 256>>>(x, Wih, bih, bhh);
    rnn_scan_kernel<<<NB / 2, 128>>>(Whh, fcw, fcb, out);
}

// round 6
// speedup vs baseline: 1.6233x; 1.1579x over previous
#include <cuda_runtime.h>
#include <cstdint>

#define NB 256
#define NT 512
#define NI 300
#define NH 128

typedef unsigned long long u64t;

// 64 MiB scratch for precomputed input projections xp[b][t][h]
__device__ float g_xp[NB * NT * NH];

// ---------------- packed f32x2 helpers (sm_103a) ----------------
__device__ __forceinline__ u64t pack2(float lo, float hi) {
    u64t r;
    asm("mov.b64 %0, {%1, %2};" : "=l"(r) : "f"(lo), "f"(hi));
    return r;
}
__device__ __forceinline__ void unpack2(u64t v, float& lo, float& hi) {
    asm("mov.b64 {%0, %1}, %2;" : "=f"(lo), "=f"(hi) : "l"(v));
}
__device__ __forceinline__ void ffma2(u64t& d, u64t a, u64t b) {
    asm("fma.rn.f32x2 %0, %1, %2, %0;" : "+l"(d) : "l"(a), "l"(b));
}
__device__ __forceinline__ void cp_async4(uint32_t s, const void* g) {
    asm volatile("cp.async.ca.shared.global [%0], [%1], 4;" :: "r"(s), "l"(g));
}

// ---------------------------------------------------------------------------
// Phase 1: xp = x @ W_ih^T + (b_ih + b_hh)
// M = 131072, N = 128, K = 300. BM=BN=128, BK=20 (300 = 15*20).
// 256 threads, 8x8 micro-tile, FFMA2 inner product, cp.async double-buffered
// tile pipeline, 2 CTAs/SM.
// ---------------------------------------------------------------------------
#define BM 128
#define BN 128
#define BK 20
#define BMP (BM + 4)   // padded row to break k-major store conflicts
#define NTILES (NI / BK)

__global__ __launch_bounds__(256, 2) void gemm_xp_kernel(
    const float* __restrict__ x, const float* __restrict__ Wih,
    const float* __restrict__ bih, const float* __restrict__ bhh)
{
    __shared__ __align__(16) float xs[2][BK][BMP];
    __shared__ __align__(16) float ws[2][BK][BMP];
    __shared__ float bias_s[NH];

    const int tid = threadIdx.x;
    const int m0 = blockIdx.x * BM;
    if (tid < NH) bias_s[tid] = bih[tid] + bhh[tid];

    const int tr = tid >> 4;   // rows tr*8 .. tr*8+7
    const int tc = tid & 15;   // cols tc*8 .. tc*8+7

    // loop-invariant load offsets: idx = tid + it*256 -> (r, kk)
    uint32_t offS[10];
    int offG[10];
#pragma unroll
    for (int it = 0; it < 10; it++) {
        int idx = tid + it * 256;
        int r = idx / BK, kk = idx % BK;
        offS[it] = (uint32_t)(kk * BMP + r) * 4u;
        offG[it] = r * NI + kk;
    }

    const uint32_t xsb0 = (uint32_t)__cvta_generic_to_shared(&xs[0][0][0]);
    const uint32_t xsb1 = (uint32_t)__cvta_generic_to_shared(&xs[1][0][0]);
    const uint32_t wsb0 = (uint32_t)__cvta_generic_to_shared(&ws[0][0][0]);
    const uint32_t wsb1 = (uint32_t)__cvta_generic_to_shared(&ws[1][0][0]);

    const float* xg = x + (long)m0 * NI;

    u64t acc2[8][4];
#pragma unroll
    for (int i = 0; i < 8; i++)
#pragma unroll
        for (int p = 0; p < 4; p++) acc2[i][p] = 0ull;

#define ISSUE_TILE(tile, xsb, wsb)                                   \
    do {                                                             \
        const float* xt_ = xg + (tile) * BK;                         \
        const float* wt_ = Wih + (tile) * BK;                        \
        _Pragma("unroll")                                            \
        for (int it = 0; it < 10; it++) {                            \
            cp_async4((xsb) + offS[it], xt_ + offG[it]);             \
            cp_async4((wsb) + offS[it], wt_ + offG[it]);             \
        }                                                            \
        asm volatile("cp.async.commit_group;");                      \
    } while (0)

    ISSUE_TILE(0, xsb0, wsb0);

    for (int tile = 0; tile < NTILES; tile++) {
        int buf = tile & 1;
        if (tile + 1 < NTILES) {
            if (buf == 0) ISSUE_TILE(tile + 1, xsb1, wsb1);
            else          ISSUE_TILE(tile + 1, xsb0, wsb0);
            asm volatile("cp.async.wait_group 1;");
        } else {
            asm volatile("cp.async.wait_group 0;");
        }
        __syncthreads();

        const float(*xsp)[BMP] = xs[buf];
        const float(*wsp)[BMP] = ws[buf];
#pragma unroll 4
        for (int kk = 0; kk < BK; kk++) {
            float4 a0 = *(const float4*)&xsp[kk][tr * 8];
            float4 a1 = *(const float4*)&xsp[kk][tr * 8 + 4];
            ulonglong2 bq0 = *(const ulonglong2*)&wsp[kk][tc * 8];
            ulonglong2 bq1 = *(const ulonglong2*)&wsp[kk][tc * 8 + 4];
            u64t bp[4] = {bq0.x, bq0.y, bq1.x, bq1.y};
            float av[8] = {a0.x, a0.y, a0.z, a0.w, a1.x, a1.y, a1.z, a1.w};
#pragma unroll
            for (int i = 0; i < 8; i++) {
                u64t ap = pack2(av[i], av[i]);
#pragma unroll
                for (int p = 0; p < 4; p++)
                    ffma2(acc2[i][p], ap, bp[p]);
            }
        }
        __syncthreads();   // protect buf before next overwrite
    }
#undef ISSUE_TILE

    // epilogue: unpack, add bias, store
#pragma unroll
    for (int i = 0; i < 8; i++) {
        int r = m0 + tr * 8 + i;
        float* pdst = &g_xp[r * NH + tc * 8];
#pragma unroll
        for (int p = 0; p < 4; p++) {
            float lo, hi;
            unpack2(acc2[i][p], lo, hi);
            float2 v;
            v.x = lo + bias_s[tc * 8 + 2 * p];
            v.y = hi + bias_s[tc * 8 + 2 * p + 1];
            *(float2*)(pdst + 2 * p) = v;
        }
    }
}

// ---------------------------------------------------------------------------
// Phase 2: scan with k-split. 128 CTAs x 256 threads, 2 batch rows/CTA.
// Thread tid = 2*j + half computes the `half` 64-term slice of dot product j
// for BOTH rows; pair lanes (adjacent, same warp) combine with ONE shfl_xor.
// 2 warps/SMSP -> latency hiding. Per thread/step: 32 FFMA2 + 16 LDS.128
// + 1 shfl + 1 tanh + 1 STS + 1 LDG(prefetch, depth 2).
// ---------------------------------------------------------------------------
__global__ __launch_bounds__(256, 1) void rnn_scan_kernel(
    const float* __restrict__ Whh, const float* __restrict__ fcw,
    const float* __restrict__ fcb, float* __restrict__ out)
{
    __shared__ __align__(16) float hbuf[2][2][NH];

    const int tid = threadIdx.x;
    const int j = tid >> 1;
    const int half = tid & 1;
    const int b0 = blockIdx.x * 2;
    const int kb = half * 64;

    // this thread's 64-weight slice of row j, as 32 packed pairs
    u64t w2[32];
    const ulonglong2* wp = (const ulonglong2*)(Whh + j * NH + kb);
#pragma unroll
    for (int i = 0; i < 16; i++) {
        ulonglong2 v = wp[i];
        w2[2 * i] = v.x;
        w2[2 * i + 1] = v.y;
    }

    hbuf[0][half][j] = 0.f;
    __syncthreads();

    // xp stream for the row this thread writes (row = half)
    const float* __restrict__ xq = g_xp + (long)(b0 + half) * (NT * NH);
    float nxa = xq[j];
    float nxb = xq[NH + j];

    int cur = 0;
    for (int t = 0; t < NT; t++) {
        float xv = nxa;
        nxa = nxb;
        if (t + 2 < NT) nxb = xq[(t + 2) * NH + j];

        // two packed chains per batch row (partial dot over 64 k's)
        u64t c0a = 0ull, c0b = 0ull, c1a = 0ull, c1b = 0ull;
        const float* h0 = hbuf[cur][0] + kb;
        const float* h1 = hbuf[cur][1] + kb;
#pragma unroll
        for (int k = 0; k < 64; k += 4) {
            ulonglong2 p = *(const ulonglong2*)(h0 + k);
            ulonglong2 q = *(const ulonglong2*)(h1 + k);
            ffma2(c0a, p.x, w2[k / 2]);
            ffma2(c1a, q.x, w2[k / 2]);
            ffma2(c0b, p.y, w2[k / 2 + 1]);
            ffma2(c1b, q.y, w2[k / 2 + 1]);
        }

        float a, b, c, d;
        unpack2(c0a, a, b); unpack2(c0b, c, d);
        float s0 = (a + b) + (c + d);       // my partial of row0 dot j
        unpack2(c1a, a, b); unpack2(c1b, c, d);
        float s1 = (a + b) + (c + d);       // my partial of row1 dot j

        // single exchange: send the partial my partner needs
        float send = half ? s0 : s1;
        float recv = __shfl_xor_sync(0xffffffffu, send, 1);
        float mysum = (half ? s1 : s0) + recv;

        int nxt = cur ^ 1;
        hbuf[nxt][half][j] = tanhf(mysum + xv);
        __syncthreads();
        cur = nxt;
    }

    // fused FC (128 -> 2): first 4 warps, warp w -> (row = w>>1, class = w&1)
    if (tid < 128) {
        const int w = tid >> 5, lane = tid & 31;
        const int row = w >> 1, cls = w & 1;
        const float* h = hbuf[cur][row];
        float s = 0.f;
#pragma unroll
        for (int kk = 0; kk < NH; kk += 32)
            s += h[kk + lane] * fcw[cls * NH + kk + lane];
#pragma unroll
        for (int off = 16; off > 0; off >>= 1)
            s += __shfl_xor_sync(0xffffffffu, s, off);
        if (lane == 0) out[(b0 + row) * 2 + cls] = s + fcb[cls];
    }
}

// ---------------------------------------------------------------------------
extern "C" void kernel_launch(void* const* d_in, const int* in_sizes, int n_in,
                              void* d_out, int out_size)
{
    const float* x   = (const float*)d_in[0];
    const float* Wih = (const float*)d_in[1];
    const float* Whh = (const float*)d_in[2];
    const float* bih = (const float*)d_in[3];
    const float* bhh = (const float*)d_in[4];
    const float* fcw = (const float*)d_in[5];
    const float* fcb = (const float*)d_in[6];
    float* out = (float*)d_out;

    (void)in_sizes; (void)n_in; (void)out_size;

    gemm_xp_kernel<<<(NB * NT) / BM, 256>>>(x, Wih, bih, bhh);
    rnn_scan_kernel<<<NB / 2, 256>>>(Whh, fcw, fcb, out);
}

// round 8
// speedup vs baseline: 1.6609x; 1.0232x over previous
#include <cuda_runtime.h>
#include <cstdint>

#define NB 256
#define NT 512
#define NI 300
#define NH 128

typedef unsigned long long u64t;

// 64 MiB scratch for precomputed input projections xp[b][t][h]
__device__ float g_xp[NB * NT * NH];

// ---------------- packed f32x2 helpers (sm_103a) ----------------
__device__ __forceinline__ u64t pack2(float lo, float hi) {
    u64t r;
    asm("mov.b64 %0, {%1, %2};" : "=l"(r) : "f"(lo), "f"(hi));
    return r;
}
__device__ __forceinline__ void unpack2(u64t v, float& lo, float& hi) {
    asm("mov.b64 {%0, %1}, %2;" : "=f"(lo), "=f"(hi) : "l"(v));
}
__device__ __forceinline__ void ffma2(u64t& d, u64t a, u64t b) {
    asm("fma.rn.f32x2 %0, %1, %2, %0;" : "+l"(d) : "l"(a), "l"(b));
}
__device__ __forceinline__ void cp_async4(uint32_t s, const void* g) {
    asm volatile("cp.async.ca.shared.global [%0], [%1], 4;" :: "r"(s), "l"(g));
}

// ---------------------------------------------------------------------------
// Phase 1: xp = x @ W_ih^T + (b_ih + b_hh)   (unchanged from round 6)
// ---------------------------------------------------------------------------
#define BM 128
#define BN 128
#define BK 20
#define BMP (BM + 4)
#define NTILES (NI / BK)

__global__ __launch_bounds__(256, 2) void gemm_xp_kernel(
    const float* __restrict__ x, const float* __restrict__ Wih,
    const float* __restrict__ bih, const float* __restrict__ bhh)
{
    __shared__ __align__(16) float xs[2][BK][BMP];
    __shared__ __align__(16) float ws[2][BK][BMP];
    __shared__ float bias_s[NH];

    const int tid = threadIdx.x;
    const int m0 = blockIdx.x * BM;
    if (tid < NH) bias_s[tid] = bih[tid] + bhh[tid];

    const int tr = tid >> 4;
    const int tc = tid & 15;

    uint32_t offS[10];
    int offG[10];
#pragma unroll
    for (int it = 0; it < 10; it++) {
        int idx = tid + it * 256;
        int r = idx / BK, kk = idx % BK;
        offS[it] = (uint32_t)(kk * BMP + r) * 4u;
        offG[it] = r * NI + kk;
    }

    const uint32_t xsb0 = (uint32_t)__cvta_generic_to_shared(&xs[0][0][0]);
    const uint32_t xsb1 = (uint32_t)__cvta_generic_to_shared(&xs[1][0][0]);
    const uint32_t wsb0 = (uint32_t)__cvta_generic_to_shared(&ws[0][0][0]);
    const uint32_t wsb1 = (uint32_t)__cvta_generic_to_shared(&ws[1][0][0]);

    const float* xg = x + (long)m0 * NI;

    u64t acc2[8][4];
#pragma unroll
    for (int i = 0; i < 8; i++)
#pragma unroll
        for (int p = 0; p < 4; p++) acc2[i][p] = 0ull;

#define ISSUE_TILE(tile, xsb, wsb)                                   \
    do {                                                             \
        const float* xt_ = xg + (tile) * BK;                         \
        const float* wt_ = Wih + (tile) * BK;                        \
        _Pragma("unroll")                                            \
        for (int it = 0; it < 10; it++) {                            \
            cp_async4((xsb) + offS[it], xt_ + offG[it]);             \
            cp_async4((wsb) + offS[it], wt_ + offG[it]);             \
        }                                                            \
        asm volatile("cp.async.commit_group;");                      \
    } while (0)

    ISSUE_TILE(0, xsb0, wsb0);

    for (int tile = 0; tile < NTILES; tile++) {
        int buf = tile & 1;
        if (tile + 1 < NTILES) {
            if (buf == 0) ISSUE_TILE(tile + 1, xsb1, wsb1);
            else          ISSUE_TILE(tile + 1, xsb0, wsb0);
            asm volatile("cp.async.wait_group 1;");
        } else {
            asm volatile("cp.async.wait_group 0;");
        }
        __syncthreads();

        const float(*xsp)[BMP] = xs[buf];
        const float(*wsp)[BMP] = ws[buf];
#pragma unroll 4
        for (int kk = 0; kk < BK; kk++) {
            float4 a0 = *(const float4*)&xsp[kk][tr * 8];
            float4 a1 = *(const float4*)&xsp[kk][tr * 8 + 4];
            ulonglong2 bq0 = *(const ulonglong2*)&wsp[kk][tc * 8];
            ulonglong2 bq1 = *(const ulonglong2*)&wsp[kk][tc * 8 + 4];
            u64t bp[4] = {bq0.x, bq0.y, bq1.x, bq1.y};
            float av[8] = {a0.x, a0.y, a0.z, a0.w, a1.x, a1.y, a1.z, a1.w};
#pragma unroll
            for (int i = 0; i < 8; i++) {
                u64t ap = pack2(av[i], av[i]);
#pragma unroll
                for (int p = 0; p < 4; p++)
                    ffma2(acc2[i][p], ap, bp[p]);
            }
        }
        __syncthreads();
    }
#undef ISSUE_TILE

#pragma unroll
    for (int i = 0; i < 8; i++) {
        int r = m0 + tr * 8 + i;
        float* pdst = &g_xp[r * NH + tc * 8];
#pragma unroll
        for (int p = 0; p < 4; p++) {
            float lo, hi;
            unpack2(acc2[i][p], lo, hi);
            float2 v;
            v.x = lo + bias_s[tc * 8 + 2 * p];
            v.y = hi + bias_s[tc * 8 + 2 * p + 1];
            *(float2*)(pdst + 2 * p) = v;
        }
    }
}

// ---------------------------------------------------------------------------
// Phase 2: scan with output-register blocking.
// 128 CTAs x 256 threads, 2 batch rows/CTA.
// Thread (jg = tid>>3, ks = tid&7) computes 4 outputs j = jg*4..jg*4+3 over a
// STRIDED k-slice {i*32 + ks*4 .. +3 : i=0..3} for BOTH rows.
//   - reuse: each loaded h value feeds 4 FMAs (8 FFMA2 per LDS.128)
//   - loads: octet reads 8 consecutive 16B lines -> conflict-free broadcast
//   - reduction: 7-shuffle butterfly over the 8-lane octet; lane ks ends up
//     owning output (j = jg*4 + (ks>>1), row = ks&1)
// Per thread/step: 64 FFMA2 + 8 LDS.128 + 7 SHFL + 1 tanh + 1 STS + 1 LDG.
// ---------------------------------------------------------------------------
#define HSTRIDE 144   // ≡16 (mod 32) banks: separates row0/row1 STS banks

__global__ __launch_bounds__(256, 1) void rnn_scan_kernel(
    const float* __restrict__ Whh, const float* __restrict__ fcw,
    const float* __restrict__ fcb, float* __restrict__ out)
{
    __shared__ __align__(16) float hbuf[2][2][HSTRIDE];

    const int tid = threadIdx.x;
    const int jg = tid >> 3;        // 0..31
    const int ks = tid & 7;         // 0..7
    const int j0 = jg * 4;
    const int b0 = blockIdx.x * 2;

    // weights: w2[jl][2i+c] = {W[j0+jl][i*32+ks*4 + 2c], W[...+2c+1]}
    u64t w2[4][8];
#pragma unroll
    for (int jl = 0; jl < 4; jl++) {
        const ulonglong2* wp = (const ulonglong2*)(Whh + (j0 + jl) * NH);
#pragma unroll
        for (int i = 0; i < 4; i++) {
            ulonglong2 v = wp[i * 8 + ks];   // float idx i*32+ks*4
            w2[jl][2 * i] = v.x;
            w2[jl][2 * i + 1] = v.y;
        }
    }

    // my final output after the butterfly
    const int row = ks & 1;
    const int jmine = j0 + (ks >> 1);

    hbuf[0][tid & 1][tid >> 1] = 0.f;
    __syncthreads();

    const float* __restrict__ xq = g_xp + (long)(b0 + row) * (NT * NH);
    float nxa = xq[jmine];
    float nxb = xq[NH + jmine];

    int cur = 0;
    for (int t = 0; t < NT; t++) {
        float xv = nxa;
        nxa = nxb;
        if (t + 2 < NT) nxb = xq[(t + 2) * NH + jmine];

        const float* h0 = &hbuf[cur][0][0];
        const float* h1 = &hbuf[cur][1][0];

        u64t c[4][2];
#pragma unroll
        for (int jl = 0; jl < 4; jl++) { c[jl][0] = 0ull; c[jl][1] = 0ull; }

#pragma unroll
        for (int i = 0; i < 4; i++) {
            ulonglong2 p = *(const ulonglong2*)(h0 + i * 32 + ks * 4);
            ulonglong2 q = *(const ulonglong2*)(h1 + i * 32 + ks * 4);
#pragma unroll
            for (int jl = 0; jl < 4; jl++) {
                ffma2(c[jl][0], p.x, w2[jl][2 * i]);
                ffma2(c[jl][1], q.x, w2[jl][2 * i]);
                ffma2(c[jl][0], p.y, w2[jl][2 * i + 1]);
                ffma2(c[jl][1], q.y, w2[jl][2 * i + 1]);
            }
        }

        // s[m], m = jl*2 + r
        float s[8];
#pragma unroll
        for (int jl = 0; jl < 4; jl++) {
#pragma unroll
            for (int r = 0; r < 2; r++) {
                float lo, hi;
                unpack2(c[jl][r], lo, hi);
                s[jl * 2 + r] = lo + hi;
            }
        }

        // butterfly over octet: lane ks ends with total of s[ks]
        const int k4 = ks & 4, k2 = ks & 2, k1 = ks & 1;
        float t4[4];
#pragma unroll
        for (int i = 0; i < 4; i++) {
            float rcv = __shfl_xor_sync(0xffffffffu, s[i + (k4 ^ 4)], 4);
            t4[i] = s[i + k4] + rcv;
        }
        float t2[2];
#pragma unroll
        for (int i = 0; i < 2; i++) {
            float rcv = __shfl_xor_sync(0xffffffffu, t4[i + (k2 ^ 2)], 2);
            t2[i] = t4[i + k2] + rcv;
        }
        float rsum;
        {
            float rcv = __shfl_xor_sync(0xffffffffu, t2[k1 ^ 1], 1);
            rsum = t2[k1] + rcv;
        }

        int nxt = cur ^ 1;
        hbuf[nxt][row][jmine] = tanhf(rsum + xv);
        __syncthreads();
        cur = nxt;
    }

    // fused FC (128 -> 2): first 4 warps, warp w -> (row = w>>1, class = w&1)
    if (tid < 128) {
        const int w = tid >> 5, lane = tid & 31;
        const int frow = w >> 1, cls = w & 1;
        const float* h = &hbuf[cur][frow][0];
        float s2 = 0.f;
#pragma unroll
        for (int kk = 0; kk < NH; kk += 32)
            s2 += h[kk + lane] * fcw[cls * NH + kk + lane];
#pragma unroll
        for (int off = 16; off > 0; off >>= 1)
            s2 += __shfl_xor_sync(0xffffffffu, s2, off);
        if (lane == 0) out[(b0 + frow) * 2 + cls] = s2 + fcb[cls];
    }
}

// ---------------------------------------------------------------------------
extern "C" void kernel_launch(void* const* d_in, const int* in_sizes, int n_in,
                              void* d_out, int out_size)
{
    const float* x   = (const float*)d_in[0];
    const float* Wih = (const float*)d_in[1];
    const float* Whh = (const float*)d_in[2];
    const float* bih = (const float*)d_in[3];
    const float* bhh = (const float*)d_in[4];
    const float* fcw = (const float*)d_in[5];
    const float* fcb = (const float*)d_in[6];
    float* out = (float*)d_out;

    (void)in_sizes; (void)n_in; (void)out_size;

    gemm_xp_kernel<<<(NB * NT) / BM, 256>>>(x, Wih, bih, bhh);
    rnn_scan_kernel<<<NB / 2, 256>>>(Whh, fcw, fcb, out);
}